// round 3
// baseline (speedup 1.0000x reference)
#include <cuda_runtime.h>

#define BMAX 16384
#define L 16
#define D 8
#define U 128
#define P 8

// ---- composed-weight + softmax scratch (static device arrays; no allocs) ----
__device__ float g_WqT[D*U],  g_bq[U];   // sq_w composed with le_w (transposed [d][u])
__device__ float g_WrT[D*U],  g_br[U];   // sr_w composed
__device__ float g_WaqT[D*U], g_caq[U];  // aq_w composed (caq = aq_w@le_b)
__device__ float g_WarT[D*U], g_car[U];  // ar_w composed
__device__ float g_logits[(size_t)BMAX*L];
__device__ float g_invden[L];

// Native MUFU tanh (measured output rel_err ~5e-6 end to end)
__device__ __forceinline__ float fast_tanh(float x) {
    float y;
    asm("tanh.approx.f32 %0, %1;" : "=f"(y) : "f"(x));
    return y;
}

// Multi-value halving butterfly: reduces v[0..7] across all 32 lanes.
// After return, v[0] on lane r holds the 32-lane sum of value index rev3(r&7).
__device__ __forceinline__ void red8(float v[8], int lane) {
#pragma unroll
    for (int m = 1; m <= 4; m <<= 1) {
        int n = (m == 1) ? 8 : (m == 2) ? 4 : 2;
        int h = n >> 1;
        bool up = (lane & m) != 0;
#pragma unroll
        for (int i = 0; i < 4; i++) {
            if (i < h) {
                float send = up ? v[i] : v[i + h];
                float recv = __shfl_xor_sync(0xffffffffu, send, m);
                v[i] = (up ? v[i + h] : v[i]) + recv;
            }
        }
    }
    v[0] += __shfl_xor_sync(0xffffffffu, v[0], 8);
    v[0] += __shfl_xor_sync(0xffffffffu, v[0], 16);
}

__device__ __forceinline__ int rev3(int r) {
    return ((r & 1) << 2) | (r & 2) | ((r & 4) >> 2);
}

// ---------------------------------------------------------------------------
// Kernel 0: fold le_w/le_b through the four 128x128 linears. Split-K over 2
// thread halves. grid.x = 4 (matrix id), 256 threads.
// ---------------------------------------------------------------------------
__global__ void k_compose(const float* __restrict__ le_w, const float* __restrict__ le_b,
                          const float* __restrict__ sq_w, const float* __restrict__ sq_b,
                          const float* __restrict__ sr_w, const float* __restrict__ sr_b,
                          const float* __restrict__ aq_w,
                          const float* __restrict__ ar_w) {
    __shared__ float sle[U*D], sleb[U];
    __shared__ float spart[U][D + 1];
    int tid = threadIdx.x;
    int u = tid & 127, half = tid >> 7;
    if (half == 0) {
#pragma unroll
        for (int d = 0; d < D; d++) sle[u*D + d] = le_w[u*D + d];
        sleb[u] = le_b[u];
    }
    __syncthreads();

    int m = blockIdx.x;
    const float* W = (m == 0) ? sq_w : (m == 1) ? sr_w : (m == 2) ? aq_w : ar_w;

    float acc[D];
#pragma unroll
    for (int d = 0; d < D; d++) acc[d] = 0.0f;
    float ab = 0.0f;
    int k0 = half * (U/2);
    for (int k = k0; k < k0 + U/2; k++) {
        float w = W[u*U + k];
        ab = fmaf(w, sleb[k], ab);
#pragma unroll
        for (int d = 0; d < D; d++) acc[d] = fmaf(w, sle[k*D + d], acc[d]);
    }
    if (half == 1) {
#pragma unroll
        for (int d = 0; d < D; d++) spart[u][d] = acc[d];
        spart[u][D] = ab;
    }
    __syncthreads();
    if (half == 0) {
#pragma unroll
        for (int d = 0; d < D; d++) acc[d] += spart[u][d];
        ab += spart[u][D];
        float* WT = (m == 0) ? g_WqT : (m == 1) ? g_WrT : (m == 2) ? g_WaqT : g_WarT;
#pragma unroll
        for (int d = 0; d < D; d++) WT[d*U + u] = acc[d];
        if      (m == 0) g_bq[u]  = ab + sq_b[u];
        else if (m == 1) g_br[u]  = ab + sr_b[u];
        else if (m == 2) g_caq[u] = ab;
        else             g_car[u] = ab;
    }
}

// ---------------------------------------------------------------------------
// Kernel 1: attention logits. One warp per batch element, 8 warps/block.
// Two passes of 2 units/lane to keep regs <= 64 (4 blocks/SM).
// ---------------------------------------------------------------------------
__global__ void __launch_bounds__(256, 4) k_logits(const float* __restrict__ states,
                                                   const float* __restrict__ sa_w,
                                                   const float* __restrict__ sa_b, int B) {
    __shared__ float sWq[D*U], sWr[D*U], sbq[U], sbr[U], ssw[U];
    __shared__ float sx[8][L*D];
    int tid = threadIdx.x;
    for (int i = tid; i < D*U; i += 256) { sWq[i] = g_WqT[i]; sWr[i] = g_WrT[i]; }
    if (tid < U) { sbq[tid] = g_bq[tid]; sbr[tid] = g_br[tid]; ssw[tid] = sa_w[tid]; }
    __syncthreads();

    int warp = tid >> 5, lane = tid & 31;
    int b = blockIdx.x * 8 + warp;
    if (b >= B) b = B - 1;   // duplicate work writes identical values

    const float* xs = states + (size_t)b * (L*D + 1) + 1;
#pragma unroll
    for (int i = 0; i < 4; i++) sx[warp][lane + 32*i] = xs[lane + 32*i];
    __syncwarp();

    // mean over the 16 lanes per input dim (lanes 0..7 compute, broadcast)
    float mv = 0.0f;
    if (lane < D) {
#pragma unroll
        for (int l = 0; l < L; l++) mv += sx[warp][l*D + lane];
        mv *= (1.0f / 16.0f);
    }
    float mean[D];
#pragma unroll
    for (int d = 0; d < D; d++) mean[d] = __shfl_sync(0xffffffffu, mv, d);

    float sab = *sa_b;
    float v[2][8];
#pragma unroll
    for (int g = 0; g < 2; g++)
#pragma unroll
        for (int i = 0; i < 8; i++) v[g][i] = 0.0f;

#pragma unroll
    for (int pass = 0; pass < 2; pass++) {
        // 2 units per lane for this pass; fold ref+bq into one constant
        float wq2[2][D], c2[2], sw2[2];
#pragma unroll
        for (int jj = 0; jj < 2; jj++) {
            int u = lane + 32*(pass*2 + jj);
            float r = sbr[u];
#pragma unroll
            for (int d = 0; d < D; d++) {
                wq2[jj][d] = sWq[d*U + u];
                r = fmaf(mean[d], sWr[d*U + u], r);
            }
            c2[jj] = r + sbq[u];
            sw2[jj] = ssw[u];
        }
#pragma unroll
        for (int g = 0; g < 2; g++) {
#pragma unroll
            for (int i = 0; i < 8; i++) {
                int l = g*8 + i;
                float xl[D];
#pragma unroll
                for (int d = 0; d < D; d++) xl[d] = sx[warp][l*D + d];
#pragma unroll
                for (int jj = 0; jj < 2; jj++) {
                    float q = c2[jj];
#pragma unroll
                    for (int d = 0; d < D; d++) q = fmaf(xl[d], wq2[jj][d], q);
                    v[g][i] = fmaf(fast_tanh(q), sw2[jj], v[g][i]);
                }
            }
        }
    }
#pragma unroll
    for (int g = 0; g < 2; g++) {
        red8(v[g], lane);
        if (lane < 8) g_logits[(size_t)b*L + g*8 + rev3(lane)] = v[g][0] + sab;
    }
}

// ---------------------------------------------------------------------------
// Kernel 2: softmax denominator over the BATCH axis (one block per lane l).
// ---------------------------------------------------------------------------
__global__ void k_softmax_den(int B) {
    int l = blockIdx.x;
    int tid = threadIdx.x;
    float s = 0.0f;
    for (int b = tid; b < B; b += 1024) s += __expf(g_logits[(size_t)b*L + l]);
    __shared__ float red[1024];
    red[tid] = s;
    __syncthreads();
    for (int o = 512; o > 0; o >>= 1) {
        if (tid < o) red[tid] += red[tid + o];
        __syncthreads();
    }
    if (tid == 0) g_invden[l] = 1.0f / red[0];
}

// ---------------------------------------------------------------------------
// Kernel 3: output. One warp per batch element, two passes of 2 units/lane.
// ---------------------------------------------------------------------------
__global__ void __launch_bounds__(256, 4) k_out(const float* __restrict__ states,
                                                const float* __restrict__ aq_b,
                                                const float* __restrict__ ar_b,
                                                const float* __restrict__ aa_w,
                                                const float* __restrict__ aa_b,
                                                const int*   __restrict__ pp,
                                                float* __restrict__ out, int B) {
    __shared__ float sWaq[D*U], sWar[D*U], scaq[U], scar[U], sba[U], sarb[U], saw[U];
    __shared__ float sx[8][L*D];
    __shared__ float sat[8][L];
    __shared__ float sy[8][P*D];
    __shared__ float ssum[8][P];
    int tid = threadIdx.x;
    for (int i = tid; i < D*U; i += 256) { sWaq[i] = g_WaqT[i]; sWar[i] = g_WarT[i]; }
    if (tid < U) {
        scaq[tid] = g_caq[tid]; scar[tid] = g_car[tid];
        sba[tid] = aq_b[tid];   sarb[tid] = ar_b[tid]; saw[tid] = aa_w[tid];
    }
    __syncthreads();

    int warp = tid >> 5, lane = tid & 31;
    int b = blockIdx.x * 8 + warp;
    if (b >= B) b = B - 1;

    const float* row = states + (size_t)b * (L*D + 1);
#pragma unroll
    for (int i = 0; i < 4; i++) sx[warp][lane + 32*i] = row[1 + lane + 32*i];
    if (lane < L) sat[warp][lane] = __expf(g_logits[(size_t)b*L + lane]) * g_invden[lane];
    int phase = (int)row[0];
    __syncwarp();

    // y_p[d] and s_p
#pragma unroll
    for (int t = 0; t < 2; t++) {
        int idx = lane*2 + t;
        int p = idx >> 3, d = idx & 7;
        int i0 = pp[2*p], i1 = pp[2*p + 1];
        sy[warp][p*D + d] = sat[warp][i0]*sx[warp][i0*D + d] + sat[warp][i1]*sx[warp][i1*D + d];
    }
    if (lane < P) {
        int i0 = pp[2*lane], i1 = pp[2*lane + 1];
        ssum[warp][lane] = sat[warp][i0] + sat[warp][i1];
    }
    __syncwarp();

    float ydp[D];
#pragma unroll
    for (int d = 0; d < D; d++) ydp[d] = sy[warp][phase*D + d];
    float spp = ssum[warp][phase];
    float aab = *aa_b;

    float acc[P];
#pragma unroll
    for (int p = 0; p < P; p++) acc[p] = 0.0f;

#pragma unroll
    for (int pass = 0; pass < 2; pass++) {
        float wa2[2][D], gb2[2], ca2[2], aw2[2];
#pragma unroll
        for (int jj = 0; jj < 2; jj++) {
            int u = lane + 32*(pass*2 + jj);
            float g = fmaf(spp, scar[u], sarb[u]);
#pragma unroll
            for (int d = 0; d < D; d++) {
                wa2[jj][d] = sWaq[d*U + u];
                g = fmaf(ydp[d], sWar[d*U + u], g);
            }
            gb2[jj] = g + sba[u];     // green + aq_b folded
            ca2[jj] = scaq[u];
            aw2[jj] = saw[u];
        }
#pragma unroll
        for (int p = 0; p < P; p++) {
            float yd[D];
#pragma unroll
            for (int d = 0; d < D; d++) yd[d] = sy[warp][p*D + d];
            float sp = ssum[warp][p];
#pragma unroll
            for (int jj = 0; jj < 2; jj++) {
                float pq = fmaf(sp, ca2[jj], gb2[jj]);
#pragma unroll
                for (int d = 0; d < D; d++) pq = fmaf(yd[d], wa2[jj][d], pq);
                acc[p] = fmaf(fast_tanh(pq), aw2[jj], acc[p]);
            }
        }
    }
    red8(acc, lane);
    if (lane < 8) out[(size_t)b*P + rev3(lane)] = acc[0] + aab;
}

// ---------------------------------------------------------------------------
extern "C" void kernel_launch(void* const* d_in, const int* in_sizes, int n_in,
                              void* d_out, int out_size) {
    const float* states = (const float*)d_in[0];
    const float* le_w   = (const float*)d_in[1];
    const float* le_b   = (const float*)d_in[2];
    const float* sq_w   = (const float*)d_in[3];
    const float* sq_b   = (const float*)d_in[4];
    const float* sr_w   = (const float*)d_in[5];
    const float* sr_b   = (const float*)d_in[6];
    const float* sa_w   = (const float*)d_in[7];
    const float* sa_b   = (const float*)d_in[8];
    const float* aq_w   = (const float*)d_in[9];
    const float* aq_b   = (const float*)d_in[10];
    const float* ar_w   = (const float*)d_in[11];
    const float* ar_b   = (const float*)d_in[12];
    const float* aa_w   = (const float*)d_in[13];
    const float* aa_b   = (const float*)d_in[14];
    const int*   pp     = (const int*)d_in[15];
    float* out = (float*)d_out;

    int B = in_sizes[0] / (L*D + 1);
    if (B > BMAX) B = BMAX;
    int nb = (B + 7) / 8;

    k_compose<<<4, 256>>>(le_w, le_b, sq_w, sq_b, sr_w, sr_b, aq_w, ar_w);
    k_logits<<<nb, 256>>>(states, sa_w, sa_b, B);
    k_softmax_den<<<L, 1024>>>(B);
    k_out<<<nb, 256>>>(states, aq_b, ar_b, aa_w, aa_b, pp, out, B);
}

// round 4
// speedup vs baseline: 2.1484x; 2.1484x over previous
#include <cuda_runtime.h>

#define BMAX 16384
#define L 16
#define D 8
#define U 128
#define P 8

// ---- composed weights, u-major [u][d] so each lane loads 2x float4 ----
__device__ __align__(16) float g_WqU[U*D];   // sq_w o le_w
__device__ __align__(16) float g_WrU[U*D];   // sr_w o le_w
__device__ __align__(16) float g_WaqU[U*D];  // aq_w o le_w
__device__ __align__(16) float g_WarU[U*D];  // ar_w o le_w
__device__ float g_bq[U], g_br[U], g_caq[U], g_car[U];
__device__ float g_logits[(size_t)BMAX*L];
__device__ float g_invden[L];

__device__ __forceinline__ float fast_tanh(float x) {
    float y;
    asm("tanh.approx.f32 %0, %1;" : "=f"(y) : "f"(x));
    return y;
}

// Multi-value halving butterfly: reduces v[0..7] across 32 lanes.
// v[0] on lane r ends with the 32-lane sum of value index rev3(r&7).
__device__ __forceinline__ void red8(float v[8], int lane) {
#pragma unroll
    for (int m = 1; m <= 4; m <<= 1) {
        int n = (m == 1) ? 8 : (m == 2) ? 4 : 2;
        int h = n >> 1;
        bool up = (lane & m) != 0;
#pragma unroll
        for (int i = 0; i < 4; i++) {
            if (i < h) {
                float send = up ? v[i] : v[i + h];
                float recv = __shfl_xor_sync(0xffffffffu, send, m);
                v[i] = (up ? v[i + h] : v[i]) + recv;
            }
        }
    }
    v[0] += __shfl_xor_sync(0xffffffffu, v[0], 8);
    v[0] += __shfl_xor_sync(0xffffffffu, v[0], 16);
}

__device__ __forceinline__ int rev3(int r) {
    return ((r & 1) << 2) | (r & 2) | ((r & 4) >> 2);
}

__device__ __forceinline__ float dot8(const float4 a0, const float4 a1,
                                      const float* w, float init) {
    float q = init;
    q = fmaf(a0.x, w[0], q); q = fmaf(a0.y, w[1], q);
    q = fmaf(a0.z, w[2], q); q = fmaf(a0.w, w[3], q);
    q = fmaf(a1.x, w[4], q); q = fmaf(a1.y, w[5], q);
    q = fmaf(a1.z, w[6], q); q = fmaf(a1.w, w[7], q);
    return q;
}

// ---------------------------------------------------------------------------
// Kernel 0: fold le_w/le_b through the four 128x128 linears. Split-K halves.
// Writes u-major composed weights.
// ---------------------------------------------------------------------------
__global__ void k_compose(const float* __restrict__ le_w, const float* __restrict__ le_b,
                          const float* __restrict__ sq_w, const float* __restrict__ sq_b,
                          const float* __restrict__ sr_w, const float* __restrict__ sr_b,
                          const float* __restrict__ aq_w,
                          const float* __restrict__ ar_w) {
    __shared__ float sle[U*D], sleb[U];
    __shared__ float spart[U][D + 1];
    int tid = threadIdx.x;
    int u = tid & 127, half = tid >> 7;
    if (half == 0) {
#pragma unroll
        for (int d = 0; d < D; d++) sle[u*D + d] = le_w[u*D + d];
        sleb[u] = le_b[u];
    }
    __syncthreads();

    int m = blockIdx.x;
    const float* W = (m == 0) ? sq_w : (m == 1) ? sr_w : (m == 2) ? aq_w : ar_w;

    float acc[D];
#pragma unroll
    for (int d = 0; d < D; d++) acc[d] = 0.0f;
    float ab = 0.0f;
    int k0 = half * (U/2);
    for (int k = k0; k < k0 + U/2; k++) {
        float w = W[u*U + k];
        ab = fmaf(w, sleb[k], ab);
#pragma unroll
        for (int d = 0; d < D; d++) acc[d] = fmaf(w, sle[k*D + d], acc[d]);
    }
    if (half == 1) {
#pragma unroll
        for (int d = 0; d < D; d++) spart[u][d] = acc[d];
        spart[u][D] = ab;
    }
    __syncthreads();
    if (half == 0) {
#pragma unroll
        for (int d = 0; d < D; d++) acc[d] += spart[u][d];
        ab += spart[u][D];
        float* WT = (m == 0) ? g_WqU : (m == 1) ? g_WrU : (m == 2) ? g_WaqU : g_WarU;
#pragma unroll
        for (int d = 0; d < D; d++) WT[u*D + d] = acc[d];
        if      (m == 0) g_bq[u]  = ab + sq_b[u];
        else if (m == 1) g_br[u]  = ab + sr_b[u];
        else if (m == 2) g_caq[u] = ab;
        else             g_car[u] = ab;
    }
}

// ---------------------------------------------------------------------------
// Kernel 1: attention logits. One warp per batch element, 8 warps/block.
// ---------------------------------------------------------------------------
__global__ void __launch_bounds__(256) k_logits(const float* __restrict__ states,
                                                const float* __restrict__ sa_w,
                                                const float* __restrict__ sa_b, int B) {
    __shared__ __align__(16) float sx[8][L*D];
    int warp = threadIdx.x >> 5, lane = threadIdx.x & 31;
    int b = blockIdx.x * 8 + warp;
    if (b >= B) return;

    const float* xs = states + (size_t)b * (L*D + 1) + 1;
    float xv[4];
#pragma unroll
    for (int i = 0; i < 4; i++) {
        xv[i] = xs[lane + 32*i];
        sx[warp][lane + 32*i] = xv[i];
    }
    __syncwarp();

    // mean: each lane holds 4 values whose dim is lane&7; xor-reduce, broadcast
    float s = (xv[0] + xv[1]) + (xv[2] + xv[3]);
    s += __shfl_xor_sync(0xffffffffu, s, 8);
    s += __shfl_xor_sync(0xffffffffu, s, 16);
    s *= (1.0f / 16.0f);
    float mean[D];
#pragma unroll
    for (int d = 0; d < D; d++) mean[d] = __shfl_sync(0xffffffffu, s, d);

    // per-lane 4 units: weights as float4 pairs, c = ref + bq folded
    float wq[4][8], c[4], sw[4];
#pragma unroll
    for (int j = 0; j < 4; j++) {
        int u = lane + 32*j;
        float4 w0 = *(const float4*)&g_WqU[u*D];
        float4 w1 = *(const float4*)&g_WqU[u*D + 4];
        wq[j][0]=w0.x; wq[j][1]=w0.y; wq[j][2]=w0.z; wq[j][3]=w0.w;
        wq[j][4]=w1.x; wq[j][5]=w1.y; wq[j][6]=w1.z; wq[j][7]=w1.w;
        float4 r0 = *(const float4*)&g_WrU[u*D];
        float4 r1 = *(const float4*)&g_WrU[u*D + 4];
        float r = g_bq[u] + g_br[u];
        r = fmaf(mean[0], r0.x, r); r = fmaf(mean[1], r0.y, r);
        r = fmaf(mean[2], r0.z, r); r = fmaf(mean[3], r0.w, r);
        r = fmaf(mean[4], r1.x, r); r = fmaf(mean[5], r1.y, r);
        r = fmaf(mean[6], r1.z, r); r = fmaf(mean[7], r1.w, r);
        c[j] = r;
        sw[j] = sa_w[u];
    }
    float sab = *sa_b;

    const float4* sxv = (const float4*)sx[warp];
#pragma unroll
    for (int g = 0; g < 2; g++) {
        float v[8];
#pragma unroll
        for (int i = 0; i < 8; i++) {
            int l = g*8 + i;
            float4 x0 = sxv[l*2], x1 = sxv[l*2 + 1];
            float acc = 0.0f;
#pragma unroll
            for (int j = 0; j < 4; j++) {
                float q = dot8(x0, x1, wq[j], c[j]);
                acc = fmaf(fast_tanh(q), sw[j], acc);
            }
            v[i] = acc;
        }
        red8(v, lane);
        if (lane < 8) g_logits[(size_t)b*L + g*8 + rev3(lane)] = v[0] + sab;
    }
}

// ---------------------------------------------------------------------------
// Kernel 2: softmax denominator over the BATCH axis (one block per lane l).
// ---------------------------------------------------------------------------
__global__ void k_softmax_den(int B) {
    int l = blockIdx.x;
    int tid = threadIdx.x;
    float s = 0.0f;
    for (int b = tid; b < B; b += 256) s += __expf(g_logits[(size_t)b*L + l]);
    __shared__ float red[256];
    red[tid] = s;
    __syncthreads();
    for (int o = 128; o > 0; o >>= 1) {
        if (tid < o) red[tid] += red[tid + o];
        __syncthreads();
    }
    if (tid == 0) g_invden[l] = 1.0f / red[0];
}

// ---------------------------------------------------------------------------
// Kernel 3: output. One warp per batch element.
// ---------------------------------------------------------------------------
__global__ void __launch_bounds__(256) k_out(const float* __restrict__ states,
                                             const float* __restrict__ aq_b,
                                             const float* __restrict__ ar_b,
                                             const float* __restrict__ aa_w,
                                             const float* __restrict__ aa_b,
                                             const int*   __restrict__ pp,
                                             float* __restrict__ out, int B) {
    __shared__ __align__(16) float sx[8][L*D];
    __shared__ float sat[8][L];
    __shared__ __align__(16) float sy[8][P*D];
    __shared__ float ssum[8][P];
    int warp = threadIdx.x >> 5, lane = threadIdx.x & 31;
    int b = blockIdx.x * 8 + warp;
    if (b >= B) return;

    const float* row = states + (size_t)b * (L*D + 1);
#pragma unroll
    for (int i = 0; i < 4; i++) sx[warp][lane + 32*i] = row[1 + lane + 32*i];
    if (lane < L) sat[warp][lane] = __expf(g_logits[(size_t)b*L + lane]) * g_invden[lane];
    int phase = (int)row[0];
    __syncwarp();

    // y_p[d] and s_p
#pragma unroll
    for (int t = 0; t < 2; t++) {
        int idx = lane*2 + t;
        int p = idx >> 3, d = idx & 7;
        int i0 = pp[2*p], i1 = pp[2*p + 1];
        sy[warp][p*D + d] = sat[warp][i0]*sx[warp][i0*D + d] + sat[warp][i1]*sx[warp][i1*D + d];
    }
    if (lane < P) {
        int i0 = pp[2*lane], i1 = pp[2*lane + 1];
        ssum[warp][lane] = sat[warp][i0] + sat[warp][i1];
    }
    __syncwarp();

    const float4* syv = (const float4*)sy[warp];
    float4 yp0 = syv[phase*2], yp1 = syv[phase*2 + 1];
    float spp = ssum[warp][phase];
    float aab = *aa_b;

    // per-lane 4 units: green + aq_b folded into gb[j]
    float wa[4][8], gb[4], ca[4], aw[4];
#pragma unroll
    for (int j = 0; j < 4; j++) {
        int u = lane + 32*j;
        float4 w0 = *(const float4*)&g_WaqU[u*D];
        float4 w1 = *(const float4*)&g_WaqU[u*D + 4];
        wa[j][0]=w0.x; wa[j][1]=w0.y; wa[j][2]=w0.z; wa[j][3]=w0.w;
        wa[j][4]=w1.x; wa[j][5]=w1.y; wa[j][6]=w1.z; wa[j][7]=w1.w;
        float4 r0 = *(const float4*)&g_WarU[u*D];
        float4 r1 = *(const float4*)&g_WarU[u*D + 4];
        float g = fmaf(spp, g_car[u], ar_b[u]);
        g = fmaf(yp0.x, r0.x, g); g = fmaf(yp0.y, r0.y, g);
        g = fmaf(yp0.z, r0.z, g); g = fmaf(yp0.w, r0.w, g);
        g = fmaf(yp1.x, r1.x, g); g = fmaf(yp1.y, r1.y, g);
        g = fmaf(yp1.z, r1.z, g); g = fmaf(yp1.w, r1.w, g);
        gb[j] = g + aq_b[u];
        ca[j] = g_caq[u];
        aw[j] = aa_w[u];
    }

    float acc[P];
#pragma unroll
    for (int p = 0; p < P; p++) {
        float4 y0 = syv[p*2], y1 = syv[p*2 + 1];
        float sp = ssum[warp][p];
        float a = 0.0f;
#pragma unroll
        for (int j = 0; j < 4; j++) {
            float pq = dot8(y0, y1, wa[j], fmaf(sp, ca[j], gb[j]));
            a = fmaf(fast_tanh(pq), aw[j], a);
        }
        acc[p] = a;
    }
    red8(acc, lane);
    if (lane < 8) out[(size_t)b*P + rev3(lane)] = acc[0] + aab;
}

// ---------------------------------------------------------------------------
extern "C" void kernel_launch(void* const* d_in, const int* in_sizes, int n_in,
                              void* d_out, int out_size) {
    const float* states = (const float*)d_in[0];
    const float* le_w   = (const float*)d_in[1];
    const float* le_b   = (const float*)d_in[2];
    const float* sq_w   = (const float*)d_in[3];
    const float* sq_b   = (const float*)d_in[4];
    const float* sr_w   = (const float*)d_in[5];
    const float* sr_b   = (const float*)d_in[6];
    const float* sa_w   = (const float*)d_in[7];
    const float* sa_b   = (const float*)d_in[8];
    const float* aq_w   = (const float*)d_in[9];
    const float* aq_b   = (const float*)d_in[10];
    const float* ar_w   = (const float*)d_in[11];
    const float* ar_b   = (const float*)d_in[12];
    const float* aa_w   = (const float*)d_in[13];
    const float* aa_b   = (const float*)d_in[14];
    const int*   pp     = (const int*)d_in[15];
    float* out = (float*)d_out;

    int B = in_sizes[0] / (L*D + 1);
    if (B > BMAX) B = BMAX;
    int nb = (B + 7) / 8;

    k_compose<<<4, 256>>>(le_w, le_b, sq_w, sq_b, sr_w, sr_b, aq_w, ar_w);
    k_logits<<<nb, 256>>>(states, sa_w, sa_b, B);
    k_softmax_den<<<L, 256>>>(B);
    k_out<<<nb, 256>>>(states, aq_b, ar_b, aa_w, aa_b, pp, out, B);
}

// round 5
// speedup vs baseline: 2.2816x; 1.0620x over previous
#include <cuda_runtime.h>

#define BMAX 16384
#define L 16
#define D 8
#define U 128
#define P 8
#define ROW (L*D + 1)

// ---- composed weights, u-major [u][d]; consecutive 8 floats per unit ----
__device__ __align__(16) float g_WqU[U*D];   // sq_w o le_w
__device__ __align__(16) float g_WrU[U*D];   // sr_w o le_w
__device__ __align__(16) float g_WaqU[U*D];  // aq_w o le_w
__device__ __align__(16) float g_WarU[U*D];  // ar_w o le_w
__device__ float g_bqbr[U];                  // g_bq + g_br pre-summed
__device__ float g_bq[U], g_br[U], g_caq[U], g_car[U];
__device__ float g_logits[(size_t)BMAX*L];
__device__ float g_invden[L];

__device__ __forceinline__ float fast_tanh(float x) {
    float y;
    asm("tanh.approx.f32 %0, %1;" : "=f"(y) : "f"(x));
    return y;
}

// Multi-value butterfly: v[0] on lane r ends with 32-lane sum of index rev3(r&7).
__device__ __forceinline__ void red8(float v[8], int lane) {
#pragma unroll
    for (int m = 1; m <= 4; m <<= 1) {
        int n = (m == 1) ? 8 : (m == 2) ? 4 : 2;
        int h = n >> 1;
        bool up = (lane & m) != 0;
#pragma unroll
        for (int i = 0; i < 4; i++) {
            if (i < h) {
                float send = up ? v[i] : v[i + h];
                float recv = __shfl_xor_sync(0xffffffffu, send, m);
                v[i] = (up ? v[i + h] : v[i]) + recv;
            }
        }
    }
    v[0] += __shfl_xor_sync(0xffffffffu, v[0], 8);
    v[0] += __shfl_xor_sync(0xffffffffu, v[0], 16);
}

__device__ __forceinline__ int rev3(int r) {
    return ((r & 1) << 2) | (r & 2) | ((r & 4) >> 2);
}

__device__ __forceinline__ float dot8v(float4 a0, float4 a1, const float* w, float init) {
    float q = init;
    q = fmaf(a0.x, w[0], q); q = fmaf(a0.y, w[1], q);
    q = fmaf(a0.z, w[2], q); q = fmaf(a0.w, w[3], q);
    q = fmaf(a1.x, w[4], q); q = fmaf(a1.y, w[5], q);
    q = fmaf(a1.z, w[6], q); q = fmaf(a1.w, w[7], q);
    return q;
}

// ---------------------------------------------------------------------------
// Kernel 0: fold le_w/le_b through the four 128x128 linears.
// ---------------------------------------------------------------------------
__global__ void k_compose(const float* __restrict__ le_w, const float* __restrict__ le_b,
                          const float* __restrict__ sq_w, const float* __restrict__ sq_b,
                          const float* __restrict__ sr_w, const float* __restrict__ sr_b,
                          const float* __restrict__ aq_w,
                          const float* __restrict__ ar_w) {
    __shared__ float sle[U*D], sleb[U];
    __shared__ float spart[U][D + 1];
    int tid = threadIdx.x;
    int u = tid & 127, half = tid >> 7;
    if (half == 0) {
#pragma unroll
        for (int d = 0; d < D; d++) sle[u*D + d] = le_w[u*D + d];
        sleb[u] = le_b[u];
    }
    __syncthreads();

    int m = blockIdx.x;
    const float* W = (m == 0) ? sq_w : (m == 1) ? sr_w : (m == 2) ? aq_w : ar_w;

    float acc[D];
#pragma unroll
    for (int d = 0; d < D; d++) acc[d] = 0.0f;
    float ab = 0.0f;
    int k0 = half * (U/2);
    for (int k = k0; k < k0 + U/2; k++) {
        float w = W[u*U + k];
        ab = fmaf(w, sleb[k], ab);
#pragma unroll
        for (int d = 0; d < D; d++) acc[d] = fmaf(w, sle[k*D + d], acc[d]);
    }
    if (half == 1) {
#pragma unroll
        for (int d = 0; d < D; d++) spart[u][d] = acc[d];
        spart[u][D] = ab;
    }
    __syncthreads();
    if (half == 0) {
#pragma unroll
        for (int d = 0; d < D; d++) acc[d] += spart[u][d];
        ab += spart[u][D];
        float* WT = (m == 0) ? g_WqU : (m == 1) ? g_WrU : (m == 2) ? g_WaqU : g_WarU;
#pragma unroll
        for (int d = 0; d < D; d++) WT[u*D + d] = acc[d];
        if      (m == 0) g_bq[u]  = ab + sq_b[u];
        else if (m == 1) g_br[u]  = ab + sr_b[u];
        else if (m == 2) g_caq[u] = ab;
        else             g_car[u] = ab;
    }
}

__global__ void k_bsum() {
    int u = threadIdx.x;
    g_bqbr[u] = g_bq[u] + g_br[u];
}

// ---------------------------------------------------------------------------
// Kernel 1: attention logits. 128 threads = 4 warps; TWO batches per warp.
// ---------------------------------------------------------------------------
__global__ void __launch_bounds__(128) k_logits(const float* __restrict__ states,
                                                const float* __restrict__ sa_w,
                                                const float* __restrict__ sa_b, int B) {
    __shared__ __align__(16) float sx[4][2][L*D];
    int warp = threadIdx.x >> 5, lane = threadIdx.x & 31;
    int b0 = blockIdx.x * 8 + warp * 2;
    if (b0 > B - 2) b0 = B - 2;   // duplicates write identical values

    const float* xs0 = states + (size_t)b0 * ROW + 1;
    const float* xs1 = xs0 + ROW;
    float xv0[4], xv1[4];
#pragma unroll
    for (int i = 0; i < 4; i++) {
        xv0[i] = xs0[lane + 32*i];
        xv1[i] = xs1[lane + 32*i];
        sx[warp][0][lane + 32*i] = xv0[i];
        sx[warp][1][lane + 32*i] = xv1[i];
    }
    __syncwarp();

    // means: lane holds values of dim lane&7
    float s0 = (xv0[0] + xv0[1]) + (xv0[2] + xv0[3]);
    float s1 = (xv1[0] + xv1[1]) + (xv1[2] + xv1[3]);
    s0 += __shfl_xor_sync(0xffffffffu, s0, 8);
    s0 += __shfl_xor_sync(0xffffffffu, s0, 16);
    s1 += __shfl_xor_sync(0xffffffffu, s1, 8);
    s1 += __shfl_xor_sync(0xffffffffu, s1, 16);
    s0 *= (1.0f / 16.0f);
    s1 *= (1.0f / 16.0f);

    // weights (shared across both batches) + per-batch folded constants
    float wq[4][8], c0[4], c1[4], sw[4];
#pragma unroll
    for (int j = 0; j < 4; j++) {
        int u = lane + 32*j;
#pragma unroll
        for (int d = 0; d < D; d++) wq[j][d] = g_WqU[u*D + d];
        float r0 = g_bqbr[u], r1 = r0;
#pragma unroll
        for (int d = 0; d < D; d++) {
            float w = g_WrU[u*D + d];
            float m0 = __shfl_sync(0xffffffffu, s0, d);
            float m1 = __shfl_sync(0xffffffffu, s1, d);
            r0 = fmaf(m0, w, r0);
            r1 = fmaf(m1, w, r1);
        }
        c0[j] = r0; c1[j] = r1;
        sw[j] = sa_w[u];
    }
    float sab = *sa_b;

    const float4* sxv0 = (const float4*)sx[warp][0];
    const float4* sxv1 = (const float4*)sx[warp][1];
#pragma unroll
    for (int g = 0; g < 2; g++) {
        float v0[8], v1[8];
#pragma unroll
        for (int i = 0; i < 8; i++) {
            int l = g*8 + i;
            float4 a0 = sxv0[l*2], a1 = sxv0[l*2 + 1];
            float4 e0 = sxv1[l*2], e1 = sxv1[l*2 + 1];
            float acc0 = 0.0f, acc1 = 0.0f;
#pragma unroll
            for (int j = 0; j < 4; j++) {
                float q0 = dot8v(a0, a1, wq[j], c0[j]);
                float q1 = dot8v(e0, e1, wq[j], c1[j]);
                acc0 = fmaf(fast_tanh(q0), sw[j], acc0);
                acc1 = fmaf(fast_tanh(q1), sw[j], acc1);
            }
            v0[i] = acc0; v1[i] = acc1;
        }
        red8(v0, lane);
        red8(v1, lane);
        if (lane < 8) {
            int l = g*8 + rev3(lane);
            g_logits[(size_t)b0*L + l]       = v0[0] + sab;
            g_logits[(size_t)(b0 + 1)*L + l] = v1[0] + sab;
        }
    }
}

// ---------------------------------------------------------------------------
// Kernel 2: softmax denominator over the BATCH axis (one block per lane l).
// ---------------------------------------------------------------------------
__global__ void k_softmax_den(int B) {
    int l = blockIdx.x;
    int tid = threadIdx.x;
    float s = 0.0f;
    for (int b = tid; b < B; b += 256) s += __expf(g_logits[(size_t)b*L + l]);
    __shared__ float red[256];
    red[tid] = s;
    __syncthreads();
    for (int o = 128; o > 0; o >>= 1) {
        if (tid < o) red[tid] += red[tid + o];
        __syncthreads();
    }
    if (tid == 0) g_invden[l] = 1.0f / red[0];
}

// ---------------------------------------------------------------------------
// Kernel 3: output. 128 threads = 4 warps; TWO batches per warp.
// ---------------------------------------------------------------------------
__global__ void __launch_bounds__(128) k_out(const float* __restrict__ states,
                                             const float* __restrict__ aq_b,
                                             const float* __restrict__ ar_b,
                                             const float* __restrict__ aa_w,
                                             const float* __restrict__ aa_b,
                                             const int*   __restrict__ pp,
                                             float* __restrict__ out, int B) {
    __shared__ __align__(16) float sx[4][2][L*D];
    __shared__ float sat[4][2][L];
    __shared__ __align__(16) float sy[4][2][P*D];
    __shared__ float ssum[4][2][P];
    int warp = threadIdx.x >> 5, lane = threadIdx.x & 31;
    int b0 = blockIdx.x * 8 + warp * 2;
    if (b0 > B - 2) b0 = B - 2;

    const float* row0 = states + (size_t)b0 * ROW;
    const float* row1 = row0 + ROW;
#pragma unroll
    for (int i = 0; i < 4; i++) {
        sx[warp][0][lane + 32*i] = row0[1 + lane + 32*i];
        sx[warp][1][lane + 32*i] = row1[1 + lane + 32*i];
    }
    {
        int bb = lane >> 4, l = lane & 15;
        sat[warp][bb][l] = __expf(g_logits[(size_t)(b0 + bb)*L + l]) * g_invden[l];
    }
    int phase0 = (int)row0[0];
    int phase1 = (int)row1[0];
    __syncwarp();

    // y_p[d], s_p for both batches (128 y-entries over 4 steps)
#pragma unroll
    for (int t = 0; t < 4; t++) {
        int idx = lane*4 + t;
        int bb = idx >> 6, r = idx & 63;
        int p = r >> 3, d = r & 7;
        int i0 = pp[2*p], i1 = pp[2*p + 1];
        sy[warp][bb][p*D + d] = sat[warp][bb][i0]*sx[warp][bb][i0*D + d]
                              + sat[warp][bb][i1]*sx[warp][bb][i1*D + d];
    }
    if (lane < 16) {
        int bb = lane >> 3, p = lane & 7;
        int i0 = pp[2*p], i1 = pp[2*p + 1];
        ssum[warp][bb][p] = sat[warp][bb][i0] + sat[warp][bb][i1];
    }
    __syncwarp();

    const float4* syv0 = (const float4*)sy[warp][0];
    const float4* syv1 = (const float4*)sy[warp][1];
    float4 yp00 = syv0[phase0*2], yp01 = syv0[phase0*2 + 1];
    float4 yp10 = syv1[phase1*2], yp11 = syv1[phase1*2 + 1];
    float spp0 = ssum[warp][0][phase0];
    float spp1 = ssum[warp][1][phase1];
    float aab = *aa_b;

    float wa[4][8], gb0[4], gb1[4], ca[4], aw[4];
#pragma unroll
    for (int j = 0; j < 4; j++) {
        int u = lane + 32*j;
#pragma unroll
        for (int d = 0; d < D; d++) wa[j][d] = g_WaqU[u*D + d];
        float arbu = ar_b[u], caru = g_car[u];
        float wr[8];
#pragma unroll
        for (int d = 0; d < D; d++) wr[d] = g_WarU[u*D + d];
        float g0 = fmaf(spp0, caru, arbu);
        float g1 = fmaf(spp1, caru, arbu);
        g0 = dot8v(yp00, yp01, wr, g0);
        g1 = dot8v(yp10, yp11, wr, g1);
        float bau = aq_b[u];
        gb0[j] = g0 + bau;
        gb1[j] = g1 + bau;
        ca[j] = g_caq[u];
        aw[j] = aa_w[u];
    }

    float acc0[P], acc1[P];
#pragma unroll
    for (int p = 0; p < P; p++) {
        float4 y00 = syv0[p*2], y01 = syv0[p*2 + 1];
        float4 y10 = syv1[p*2], y11 = syv1[p*2 + 1];
        float sp0 = ssum[warp][0][p];
        float sp1 = ssum[warp][1][p];
        float a0 = 0.0f, a1 = 0.0f;
#pragma unroll
        for (int j = 0; j < 4; j++) {
            float pq0 = dot8v(y00, y01, wa[j], fmaf(sp0, ca[j], gb0[j]));
            float pq1 = dot8v(y10, y11, wa[j], fmaf(sp1, ca[j], gb1[j]));
            a0 = fmaf(fast_tanh(pq0), aw[j], a0);
            a1 = fmaf(fast_tanh(pq1), aw[j], a1);
        }
        acc0[p] = a0; acc1[p] = a1;
    }
    red8(acc0, lane);
    red8(acc1, lane);
    if (lane < 8) {
        int p = rev3(lane);
        out[(size_t)b0*P + p]       = acc0[0] + aab;
        out[(size_t)(b0 + 1)*P + p] = acc1[0] + aab;
    }
}

// ---------------------------------------------------------------------------
extern "C" void kernel_launch(void* const* d_in, const int* in_sizes, int n_in,
                              void* d_out, int out_size) {
    const float* states = (const float*)d_in[0];
    const float* le_w   = (const float*)d_in[1];
    const float* le_b   = (const float*)d_in[2];
    const float* sq_w   = (const float*)d_in[3];
    const float* sq_b   = (const float*)d_in[4];
    const float* sr_w   = (const float*)d_in[5];
    const float* sr_b   = (const float*)d_in[6];
    const float* sa_w   = (const float*)d_in[7];
    const float* sa_b   = (const float*)d_in[8];
    const float* aq_w   = (const float*)d_in[9];
    const float* aq_b   = (const float*)d_in[10];
    const float* ar_w   = (const float*)d_in[11];
    const float* ar_b   = (const float*)d_in[12];
    const float* aa_w   = (const float*)d_in[13];
    const float* aa_b   = (const float*)d_in[14];
    const int*   pp     = (const int*)d_in[15];
    float* out = (float*)d_out;

    int B = in_sizes[0] / ROW;
    if (B > BMAX) B = BMAX;
    int nb = (B + 7) / 8;

    k_compose<<<4, 256>>>(le_w, le_b, sq_w, sq_b, sr_w, sr_b, aq_w, ar_w);
    k_bsum<<<1, 128>>>();
    k_logits<<<nb, 128>>>(states, sa_w, sa_b, B);
    k_softmax_den<<<L, 256>>>(B);
    k_out<<<nb, 128>>>(states, aq_b, ar_b, aa_w, aa_b, pp, out, B);
}

// round 6
// speedup vs baseline: 2.5814x; 1.1314x over previous
#include <cuda_runtime.h>

#define BMAX 16384
#define L 16
#define D 8
#define U 128
#define P 8
#define ROW (L*D + 1)
#define NBMAX (BMAX/8)

// ---- composed-weight + softmax scratch (static device arrays; no allocs) ----
__device__ float g_WqT[D*U],  g_bq[U];   // sq_w composed with le_w (transposed [d][u])
__device__ float g_WrT[D*U],  g_br[U];   // sr_w composed
__device__ float g_WaqT[D*U], g_caq[U];  // aq_w composed (caq = aq_w@le_b)
__device__ float g_WarT[D*U], g_car[U];  // ar_w composed
__device__ float g_elog[(size_t)BMAX*L];    // exp(logit)
__device__ float g_part[(size_t)NBMAX*L];   // per-block partial sums of exp
__device__ float g_invden[L];

__device__ __forceinline__ float fast_tanh(float x) {
    float y;
    asm("tanh.approx.f32 %0, %1;" : "=f"(y) : "f"(x));
    return y;
}

// Multi-value butterfly: v[0] on lane r ends with 32-lane sum of index rev3(r&7).
__device__ __forceinline__ void red8(float v[8], int lane) {
#pragma unroll
    for (int m = 1; m <= 4; m <<= 1) {
        int n = (m == 1) ? 8 : (m == 2) ? 4 : 2;
        int h = n >> 1;
        bool up = (lane & m) != 0;
#pragma unroll
        for (int i = 0; i < 4; i++) {
            if (i < h) {
                float send = up ? v[i] : v[i + h];
                float recv = __shfl_xor_sync(0xffffffffu, send, m);
                v[i] = (up ? v[i + h] : v[i]) + recv;
            }
        }
    }
    v[0] += __shfl_xor_sync(0xffffffffu, v[0], 8);
    v[0] += __shfl_xor_sync(0xffffffffu, v[0], 16);
}

__device__ __forceinline__ int rev3(int r) {
    return ((r & 1) << 2) | (r & 2) | ((r & 4) >> 2);
}

// ---------------------------------------------------------------------------
// Kernel 0: fold le_w/le_b through the four 128x128 linears. Split-K halves.
// ---------------------------------------------------------------------------
__global__ void k_compose(const float* __restrict__ le_w, const float* __restrict__ le_b,
                          const float* __restrict__ sq_w, const float* __restrict__ sq_b,
                          const float* __restrict__ sr_w, const float* __restrict__ sr_b,
                          const float* __restrict__ aq_w,
                          const float* __restrict__ ar_w) {
    __shared__ float sle[U*D], sleb[U];
    __shared__ float spart[U][D + 1];
    int tid = threadIdx.x;
    int u = tid & 127, half = tid >> 7;
    if (half == 0) {
#pragma unroll
        for (int d = 0; d < D; d++) sle[u*D + d] = le_w[u*D + d];
        sleb[u] = le_b[u];
    }
    __syncthreads();

    int m = blockIdx.x;
    const float* W = (m == 0) ? sq_w : (m == 1) ? sr_w : (m == 2) ? aq_w : ar_w;

    float acc[D];
#pragma unroll
    for (int d = 0; d < D; d++) acc[d] = 0.0f;
    float ab = 0.0f;
    int k0 = half * (U/2);
    for (int k = k0; k < k0 + U/2; k++) {
        float w = W[u*U + k];
        ab = fmaf(w, sleb[k], ab);
#pragma unroll
        for (int d = 0; d < D; d++) acc[d] = fmaf(w, sle[k*D + d], acc[d]);
    }
    if (half == 1) {
#pragma unroll
        for (int d = 0; d < D; d++) spart[u][d] = acc[d];
        spart[u][D] = ab;
    }
    __syncthreads();
    if (half == 0) {
#pragma unroll
        for (int d = 0; d < D; d++) acc[d] += spart[u][d];
        ab += spart[u][D];
        float* WT = (m == 0) ? g_WqT : (m == 1) ? g_WrT : (m == 2) ? g_WaqT : g_WarT;
#pragma unroll
        for (int d = 0; d < D; d++) WT[d*U + u] = acc[d];
        if      (m == 0) g_bq[u]  = ab + sq_b[u];
        else if (m == 1) g_br[u]  = ab + sr_b[u];
        else if (m == 2) g_caq[u] = ab;
        else             g_car[u] = ab;
    }
}

// ---------------------------------------------------------------------------
// Kernel 1: attention logits -> exp(logit), plus per-block partial sums.
// One warp per batch element, 8 warps/block (round-2 structure).
// ---------------------------------------------------------------------------
__global__ void __launch_bounds__(256) k_logits(const float* __restrict__ states,
                                                const float* __restrict__ sa_w,
                                                const float* __restrict__ sa_b, int B) {
    __shared__ float sx[8][L*D];
    __shared__ float sexp[8][L];
    int tid = threadIdx.x;
    int warp = tid >> 5, lane = tid & 31;
    int borig = blockIdx.x * 8 + warp;
    bool valid = (borig < B);
    int b = valid ? borig : B - 1;

    const float* xs = states + (size_t)b * ROW + 1;
#pragma unroll
    for (int i = 0; i < 4; i++) sx[warp][lane + 32*i] = xs[lane + 32*i];
    __syncwarp();

    // mean over 16 lanes per input dim (lanes 0..7 compute, broadcast)
    float mv = 0.0f;
    if (lane < D) {
#pragma unroll
        for (int l = 0; l < L; l++) mv += sx[warp][l*D + lane];
        mv *= (1.0f / 16.0f);
    }
    float mean[D];
#pragma unroll
    for (int d = 0; d < D; d++) mean[d] = __shfl_sync(0xffffffffu, mv, d);

    // per-lane 4 units: weights in regs, c = ref + bq folded
    float wq[4][D], c[4], sw[4];
#pragma unroll
    for (int j = 0; j < 4; j++) {
        int u = lane + 32*j;
        sw[j] = sa_w[u];
        float r = g_bq[u] + g_br[u];
#pragma unroll
        for (int d = 0; d < D; d++) {
            wq[j][d] = g_WqT[d*U + u];
            r = fmaf(mean[d], g_WrT[d*U + u], r);
        }
        c[j] = r;
    }
    float sab = *sa_b;

#pragma unroll
    for (int g = 0; g < 2; g++) {
        float v[8];
#pragma unroll
        for (int i = 0; i < 8; i++) {
            int l = g*8 + i;
            float xl[D];
#pragma unroll
            for (int d = 0; d < D; d++) xl[d] = sx[warp][l*D + d];
            float acc = 0.0f;
#pragma unroll
            for (int j = 0; j < 4; j++) {
                float q = c[j];
#pragma unroll
                for (int d = 0; d < D; d++) q = fmaf(xl[d], wq[j][d], q);
                acc = fmaf(fast_tanh(q), sw[j], acc);
            }
            v[i] = acc;
        }
        red8(v, lane);
        if (lane < 8) {
            int l = g*8 + rev3(lane);
            float e = __expf(v[0] + sab);
            g_elog[(size_t)b*L + l] = e;
            sexp[warp][l] = valid ? e : 0.0f;
        }
    }
    __syncthreads();
    // deterministic fixed-order partial sum over the block's 8 warps
    if (tid < L) {
        float s = 0.0f;
#pragma unroll
        for (int w = 0; w < 8; w++) s += sexp[w][tid];
        g_part[(size_t)blockIdx.x*L + tid] = s;
    }
}

// ---------------------------------------------------------------------------
// Kernel 2: reduce per-block partials -> 1/denominator per column.
// 16 blocks x 256 threads.
// ---------------------------------------------------------------------------
__global__ void k_den(int nb) {
    int l = blockIdx.x;
    int tid = threadIdx.x;
    float s = 0.0f;
    for (int i = tid; i < nb; i += 256) s += g_part[(size_t)i*L + l];
    __shared__ float red[256];
    red[tid] = s;
    __syncthreads();
    for (int o = 128; o > 0; o >>= 1) {
        if (tid < o) red[tid] += red[tid + o];
        __syncthreads();
    }
    if (tid == 0) g_invden[l] = 1.0f / red[0];
}

// ---------------------------------------------------------------------------
// Kernel 3: output. One warp per batch element (round-2 structure).
// ---------------------------------------------------------------------------
__global__ void __launch_bounds__(256) k_out(const float* __restrict__ states,
                                             const float* __restrict__ aq_b,
                                             const float* __restrict__ ar_b,
                                             const float* __restrict__ aa_w,
                                             const float* __restrict__ aa_b,
                                             const int*   __restrict__ pp,
                                             float* __restrict__ out, int B) {
    __shared__ float sx[8][L*D];
    __shared__ float sat[8][L];
    __shared__ float sy[8][P*D];
    __shared__ float ssum[8][P];
    int warp = threadIdx.x >> 5, lane = threadIdx.x & 31;
    int b = blockIdx.x * 8 + warp;
    if (b >= B) return;

    const float* row = states + (size_t)b * ROW;
#pragma unroll
    for (int i = 0; i < 4; i++) sx[warp][lane + 32*i] = row[1 + lane + 32*i];
    if (lane < L) sat[warp][lane] = g_elog[(size_t)b*L + lane] * g_invden[lane];
    int phase = (int)row[0];
    __syncwarp();

    // y_p[d] and s_p
#pragma unroll
    for (int t = 0; t < 2; t++) {
        int idx = lane*2 + t;
        int p = idx >> 3, d = idx & 7;
        int i0 = pp[2*p], i1 = pp[2*p + 1];
        sy[warp][p*D + d] = sat[warp][i0]*sx[warp][i0*D + d] + sat[warp][i1]*sx[warp][i1*D + d];
    }
    if (lane < P) {
        int i0 = pp[2*lane], i1 = pp[2*lane + 1];
        ssum[warp][lane] = sat[warp][i0] + sat[warp][i1];
    }
    __syncwarp();

    float ydp[D];
#pragma unroll
    for (int d = 0; d < D; d++) ydp[d] = sy[warp][phase*D + d];
    float spp = ssum[warp][phase];
    float aab = *aa_b;

    // per-lane 4 units: green + aq_b folded into gb[j]
    float wa[4][D], gb[4], ca[4], aw[4];
#pragma unroll
    for (int j = 0; j < 4; j++) {
        int u = lane + 32*j;
        float g = fmaf(spp, g_car[u], ar_b[u]);
#pragma unroll
        for (int d = 0; d < D; d++) {
            wa[j][d] = g_WaqT[d*U + u];
            g = fmaf(ydp[d], g_WarT[d*U + u], g);
        }
        gb[j] = g + aq_b[u];
        ca[j] = g_caq[u];
        aw[j] = aa_w[u];
    }

    float acc[P];
#pragma unroll
    for (int p = 0; p < P; p++) {
        float yd[D];
#pragma unroll
        for (int d = 0; d < D; d++) yd[d] = sy[warp][p*D + d];
        float sp = ssum[warp][p];
        float a = 0.0f;
#pragma unroll
        for (int j = 0; j < 4; j++) {
            float pq = fmaf(sp, ca[j], gb[j]);
#pragma unroll
            for (int d = 0; d < D; d++) pq = fmaf(yd[d], wa[j][d], pq);
            a = fmaf(fast_tanh(pq), aw[j], a);
        }
        acc[p] = a;
    }
    red8(acc, lane);
    if (lane < 8) out[(size_t)b*P + rev3(lane)] = acc[0] + aab;
}

// ---------------------------------------------------------------------------
extern "C" void kernel_launch(void* const* d_in, const int* in_sizes, int n_in,
                              void* d_out, int out_size) {
    const float* states = (const float*)d_in[0];
    const float* le_w   = (const float*)d_in[1];
    const float* le_b   = (const float*)d_in[2];
    const float* sq_w   = (const float*)d_in[3];
    const float* sq_b   = (const float*)d_in[4];
    const float* sr_w   = (const float*)d_in[5];
    const float* sr_b   = (const float*)d_in[6];
    const float* sa_w   = (const float*)d_in[7];
    const float* sa_b   = (const float*)d_in[8];
    const float* aq_w   = (const float*)d_in[9];
    const float* aq_b   = (const float*)d_in[10];
    const float* ar_w   = (const float*)d_in[11];
    const float* ar_b   = (const float*)d_in[12];
    const float* aa_w   = (const float*)d_in[13];
    const float* aa_b   = (const float*)d_in[14];
    const int*   pp     = (const int*)d_in[15];
    float* out = (float*)d_out;

    int B = in_sizes[0] / ROW;
    if (B > BMAX) B = BMAX;
    int nb = (B + 7) / 8;

    k_compose<<<4, 256>>>(le_w, le_b, sq_w, sq_b, sr_w, sr_b, aq_w, ar_w);
    k_logits<<<nb, 256>>>(states, sa_w, sa_b, B);
    k_den<<<L, 256>>>(nb);
    k_out<<<nb, 256>>>(states, aq_b, ar_b, aa_w, aa_b, pp, out, B);
}

// round 7
// speedup vs baseline: 2.6074x; 1.0100x over previous
#include <cuda_runtime.h>

#define BMAX 16384
#define L 16
#define D 8
#define U 128
#define P 8
#define ROW (L*D + 1)
#define NBMAX (BMAX/8)

// ---- composed-weight + softmax scratch (static device arrays; no allocs) ----
__device__ float g_WqT[D*U],  g_bq[U];   // sq_w composed with le_w (transposed [d][u])
__device__ float g_WrT[D*U],  g_br[U];   // sr_w composed
__device__ float g_WaqT[D*U], g_caq[U];  // aq_w composed (caq = aq_w@le_b)
__device__ float g_WarT[D*U], g_car[U];  // ar_w composed
__device__ float g_elog[(size_t)BMAX*L];    // exp(logit)
__device__ float g_part[(size_t)NBMAX*L];   // per-block partial sums of exp
__device__ float g_invden[L];

__device__ __forceinline__ float fast_tanh(float x) {
    float y;
    asm("tanh.approx.f32 %0, %1;" : "=f"(y) : "f"(x));
    return y;
}

// Multi-value butterfly: v[0] on lane r ends with 32-lane sum of index rev3(r&7).
__device__ __forceinline__ void red8(float v[8], int lane) {
#pragma unroll
    for (int m = 1; m <= 4; m <<= 1) {
        int n = (m == 1) ? 8 : (m == 2) ? 4 : 2;
        int h = n >> 1;
        bool up = (lane & m) != 0;
#pragma unroll
        for (int i = 0; i < 4; i++) {
            if (i < h) {
                float send = up ? v[i] : v[i + h];
                float recv = __shfl_xor_sync(0xffffffffu, send, m);
                v[i] = (up ? v[i + h] : v[i]) + recv;
            }
        }
    }
    v[0] += __shfl_xor_sync(0xffffffffu, v[0], 8);
    v[0] += __shfl_xor_sync(0xffffffffu, v[0], 16);
}

__device__ __forceinline__ int rev3(int r) {
    return ((r & 1) << 2) | (r & 2) | ((r & 4) >> 2);
}

// dot of (a0|a1) with 8 scalar weights
__device__ __forceinline__ float dot8v(float4 a0, float4 a1, const float* w, float init) {
    float q = init;
    q = fmaf(a0.x, w[0], q); q = fmaf(a0.y, w[1], q);
    q = fmaf(a0.z, w[2], q); q = fmaf(a0.w, w[3], q);
    q = fmaf(a1.x, w[4], q); q = fmaf(a1.y, w[5], q);
    q = fmaf(a1.z, w[6], q); q = fmaf(a1.w, w[7], q);
    return q;
}

// ---------------------------------------------------------------------------
// Kernel 0: fold le_w/le_b through the four 128x128 linears. Split-K halves.
// ---------------------------------------------------------------------------
__global__ void k_compose(const float* __restrict__ le_w, const float* __restrict__ le_b,
                          const float* __restrict__ sq_w, const float* __restrict__ sq_b,
                          const float* __restrict__ sr_w, const float* __restrict__ sr_b,
                          const float* __restrict__ aq_w,
                          const float* __restrict__ ar_w) {
    __shared__ float sle[U*D], sleb[U];
    __shared__ float spart[U][D + 1];
    int tid = threadIdx.x;
    int u = tid & 127, half = tid >> 7;
    if (half == 0) {
#pragma unroll
        for (int d = 0; d < D; d++) sle[u*D + d] = le_w[u*D + d];
        sleb[u] = le_b[u];
    }
    __syncthreads();

    int m = blockIdx.x;
    const float* W = (m == 0) ? sq_w : (m == 1) ? sr_w : (m == 2) ? aq_w : ar_w;

    float acc[D];
#pragma unroll
    for (int d = 0; d < D; d++) acc[d] = 0.0f;
    float ab = 0.0f;
    int k0 = half * (U/2);
    for (int k = k0; k < k0 + U/2; k++) {
        float w = W[u*U + k];
        ab = fmaf(w, sleb[k], ab);
#pragma unroll
        for (int d = 0; d < D; d++) acc[d] = fmaf(w, sle[k*D + d], acc[d]);
    }
    if (half == 1) {
#pragma unroll
        for (int d = 0; d < D; d++) spart[u][d] = acc[d];
        spart[u][D] = ab;
    }
    __syncthreads();
    if (half == 0) {
#pragma unroll
        for (int d = 0; d < D; d++) acc[d] += spart[u][d];
        ab += spart[u][D];
        float* WT = (m == 0) ? g_WqT : (m == 1) ? g_WrT : (m == 2) ? g_WaqT : g_WarT;
#pragma unroll
        for (int d = 0; d < D; d++) WT[d*U + u] = acc[d];
        if      (m == 0) g_bq[u]  = ab + sq_b[u];
        else if (m == 1) g_br[u]  = ab + sr_b[u];
        else if (m == 2) g_caq[u] = ab;
        else             g_car[u] = ab;
    }
}

// ---------------------------------------------------------------------------
// Kernel 1: attention logits -> exp(logit), plus per-block partial sums.
// One warp per batch element, 8 warps/block; float4 LDS in the main loop.
// ---------------------------------------------------------------------------
__global__ void __launch_bounds__(256) k_logits(const float* __restrict__ states,
                                                const float* __restrict__ sa_w,
                                                const float* __restrict__ sa_b, int B) {
    __shared__ __align__(16) float sx[8][L*D];
    __shared__ float sexp[8][L];
    int tid = threadIdx.x;
    int warp = tid >> 5, lane = tid & 31;
    int borig = blockIdx.x * 8 + warp;
    bool valid = (borig < B);
    int b = valid ? borig : B - 1;

    const float* xs = states + (size_t)b * ROW + 1;
    float xv[4];
#pragma unroll
    for (int i = 0; i < 4; i++) {
        xv[i] = xs[lane + 32*i];
        sx[warp][lane + 32*i] = xv[i];
    }
    __syncwarp();

    // mean: each lane holds 4 values of dim lane&7; xor-reduce over lanes
    float mv = (xv[0] + xv[1]) + (xv[2] + xv[3]);
    mv += __shfl_xor_sync(0xffffffffu, mv, 8);
    mv += __shfl_xor_sync(0xffffffffu, mv, 16);
    mv *= (1.0f / 16.0f);
    float mean[D];
#pragma unroll
    for (int d = 0; d < D; d++) mean[d] = __shfl_sync(0xffffffffu, mv, d);

    // per-lane 4 units: weights in regs, c = ref + bq folded
    float wq[4][D], c[4], sw[4];
#pragma unroll
    for (int j = 0; j < 4; j++) {
        int u = lane + 32*j;
        sw[j] = sa_w[u];
        float r = g_bq[u] + g_br[u];
#pragma unroll
        for (int d = 0; d < D; d++) {
            wq[j][d] = g_WqT[d*U + u];
            r = fmaf(mean[d], g_WrT[d*U + u], r);
        }
        c[j] = r;
    }
    float sab = *sa_b;

    const float4* sxv = (const float4*)sx[warp];
#pragma unroll
    for (int g = 0; g < 2; g++) {
        float v[8];
#pragma unroll
        for (int i = 0; i < 8; i++) {
            int l = g*8 + i;
            float4 x0 = sxv[l*2], x1 = sxv[l*2 + 1];
            float acc = 0.0f;
#pragma unroll
            for (int j = 0; j < 4; j++) {
                float q = dot8v(x0, x1, wq[j], c[j]);
                acc = fmaf(fast_tanh(q), sw[j], acc);
            }
            v[i] = acc;
        }
        red8(v, lane);
        if (lane < 8) {
            int l = g*8 + rev3(lane);
            float e = __expf(v[0] + sab);
            g_elog[(size_t)b*L + l] = e;
            sexp[warp][l] = valid ? e : 0.0f;
        }
    }
    __syncthreads();
    // deterministic fixed-order partial sum over the block's 8 warps
    if (tid < L) {
        float s = 0.0f;
#pragma unroll
        for (int w = 0; w < 8; w++) s += sexp[w][tid];
        g_part[(size_t)blockIdx.x*L + tid] = s;
    }
}

// ---------------------------------------------------------------------------
// Kernel 2: reduce per-block partials -> 1/denominator per column.
// ---------------------------------------------------------------------------
__global__ void k_den(int nb) {
    int l = blockIdx.x;
    int tid = threadIdx.x;
    float s = 0.0f;
    for (int i = tid; i < nb; i += 256) s += g_part[(size_t)i*L + l];
    __shared__ float red[256];
    red[tid] = s;
    __syncthreads();
    for (int o = 128; o > 0; o >>= 1) {
        if (tid < o) red[tid] += red[tid + o];
        __syncthreads();
    }
    if (tid == 0) g_invden[l] = 1.0f / red[0];
}

// ---------------------------------------------------------------------------
// Kernel 3: output. One warp per batch element; float4 LDS in the main loop.
// ---------------------------------------------------------------------------
__global__ void __launch_bounds__(256) k_out(const float* __restrict__ states,
                                             const float* __restrict__ aq_b,
                                             const float* __restrict__ ar_b,
                                             const float* __restrict__ aa_w,
                                             const float* __restrict__ aa_b,
                                             const int*   __restrict__ pp,
                                             float* __restrict__ out, int B) {
    __shared__ __align__(16) float sx[8][L*D];
    __shared__ float sat[8][L];
    __shared__ __align__(16) float sy[8][P*D];
    __shared__ float ssum[8][P];
    int warp = threadIdx.x >> 5, lane = threadIdx.x & 31;
    int b = blockIdx.x * 8 + warp;
    if (b >= B) return;

    const float* row = states + (size_t)b * ROW;
#pragma unroll
    for (int i = 0; i < 4; i++) sx[warp][lane + 32*i] = row[1 + lane + 32*i];
    if (lane < L) sat[warp][lane] = g_elog[(size_t)b*L + lane] * g_invden[lane];
    int phase = (int)row[0];
    __syncwarp();

    // y_p[d] and s_p
#pragma unroll
    for (int t = 0; t < 2; t++) {
        int idx = lane*2 + t;
        int p = idx >> 3, d = idx & 7;
        int i0 = pp[2*p], i1 = pp[2*p + 1];
        sy[warp][p*D + d] = sat[warp][i0]*sx[warp][i0*D + d] + sat[warp][i1]*sx[warp][i1*D + d];
    }
    if (lane < P) {
        int i0 = pp[2*lane], i1 = pp[2*lane + 1];
        ssum[warp][lane] = sat[warp][i0] + sat[warp][i1];
    }
    __syncwarp();

    const float4* syv = (const float4*)sy[warp];
    float4 yp0 = syv[phase*2], yp1 = syv[phase*2 + 1];
    float spp = ssum[warp][phase];
    float aab = *aa_b;

    // per-lane 4 units: green + aq_b folded into gb[j]
    float wa[4][D], gb[4], ca[4], aw[4];
#pragma unroll
    for (int j = 0; j < 4; j++) {
        int u = lane + 32*j;
        float wr[D];
#pragma unroll
        for (int d = 0; d < D; d++) {
            wa[j][d] = g_WaqT[d*U + u];
            wr[d]    = g_WarT[d*U + u];
        }
        float g = fmaf(spp, g_car[u], ar_b[u]);
        g = dot8v(yp0, yp1, wr, g);
        gb[j] = g + aq_b[u];
        ca[j] = g_caq[u];
        aw[j] = aa_w[u];
    }

    float acc[P];
#pragma unroll
    for (int p = 0; p < P; p++) {
        float4 y0 = syv[p*2], y1 = syv[p*2 + 1];
        float sp = ssum[warp][p];
        float a = 0.0f;
#pragma unroll
        for (int j = 0; j < 4; j++) {
            float pq = dot8v(y0, y1, wa[j], fmaf(sp, ca[j], gb[j]));
            a = fmaf(fast_tanh(pq), aw[j], a);
        }
        acc[p] = a;
    }
    red8(acc, lane);
    if (lane < 8) out[(size_t)b*P + rev3(lane)] = acc[0] + aab;
}

// ---------------------------------------------------------------------------
extern "C" void kernel_launch(void* const* d_in, const int* in_sizes, int n_in,
                              void* d_out, int out_size) {
    const float* states = (const float*)d_in[0];
    const float* le_w   = (const float*)d_in[1];
    const float* le_b   = (const float*)d_in[2];
    const float* sq_w   = (const float*)d_in[3];
    const float* sq_b   = (const float*)d_in[4];
    const float* sr_w   = (const float*)d_in[5];
    const float* sr_b   = (const float*)d_in[6];
    const float* sa_w   = (const float*)d_in[7];
    const float* sa_b   = (const float*)d_in[8];
    const float* aq_w   = (const float*)d_in[9];
    const float* aq_b   = (const float*)d_in[10];
    const float* ar_w   = (const float*)d_in[11];
    const float* ar_b   = (const float*)d_in[12];
    const float* aa_w   = (const float*)d_in[13];
    const float* aa_b   = (const float*)d_in[14];
    const int*   pp     = (const int*)d_in[15];
    float* out = (float*)d_out;

    int B = in_sizes[0] / ROW;
    if (B > BMAX) B = BMAX;
    int nb = (B + 7) / 8;

    k_compose<<<4, 256>>>(le_w, le_b, sq_w, sq_b, sr_w, sr_b, aq_w, ar_w);
    k_logits<<<nb, 256>>>(states, sa_w, sa_b, B);
    k_den<<<L, 256>>>(nb);
    k_out<<<nb, 256>>>(states, aq_b, ar_b, aa_w, aa_b, pp, out, B);
}